// round 1
// baseline (speedup 1.0000x reference)
#include <cuda_runtime.h>
#include <math.h>

#define B_ROWS 4096
#define T_LEN  8192
#define SCAN_THREADS 512
#define CHUNK (T_LEN / SCAN_THREADS)   // 16
#define GAMMA 0.99f
#define EPS_N 1e-9f

// Scratch (no allocations allowed): global sum accumulator + per-row std.
__device__ double g_sum;
__device__ float  g_row_std[B_ROWS];

__global__ void init_kernel() {
    g_sum = 0.0;
}

// One block per row. Chunked affine suffix scan:
//   x_t = r_t + a_t * x_{t+1},  a_t = GAMMA*(1-done_t)
__global__ __launch_bounds__(SCAN_THREADS)
void scan_kernel(const float* __restrict__ rewards,
                 const float* __restrict__ dones,
                 float* __restrict__ out)
{
    const int row = blockIdx.x;
    const int tid = threadIdx.x;
    const size_t row_off = (size_t)row * T_LEN;
    const int base = tid * CHUNK;

    float r[CHUNK];
    float a[CHUNK];

    // Vectorized contiguous loads: 16 floats = 4x float4 per thread.
    const float4* r4 = reinterpret_cast<const float4*>(rewards + row_off + base);
    const float4* d4 = reinterpret_cast<const float4*>(dones   + row_off + base);
#pragma unroll
    for (int i = 0; i < CHUNK / 4; i++) {
        float4 rv = r4[i];
        float4 dv = d4[i];
        r[i*4+0] = rv.x; r[i*4+1] = rv.y; r[i*4+2] = rv.z; r[i*4+3] = rv.w;
        a[i*4+0] = GAMMA * (1.0f - dv.x);
        a[i*4+1] = GAMMA * (1.0f - dv.y);
        a[i*4+2] = GAMMA * (1.0f - dv.z);
        a[i*4+3] = GAMMA * (1.0f - dv.w);
    }

    // Local affine composition of this chunk (maps carry at right edge -> value at left edge).
    float A = 1.0f, Bc = 0.0f;
#pragma unroll
    for (int t = CHUNK - 1; t >= 0; t--) {
        Bc = fmaf(a[t], Bc, r[t]);
        A  = a[t] * A;
    }

    __shared__ float sA[SCAN_THREADS];
    __shared__ float sB[SCAN_THREADS];
    sA[tid] = A; sB[tid] = Bc;
    __syncthreads();

    // Hillis-Steele inclusive SUFFIX scan of affine composition (9 steps).
    // combine(self, next) = self ∘ next : (A1*A2, B1 + A1*B2)
#pragma unroll
    for (int off = 1; off < SCAN_THREADS; off <<= 1) {
        float na = sA[tid], nb = sB[tid];
        if (tid + off < SCAN_THREADS) {
            float a2 = sA[tid + off], b2 = sB[tid + off];
            na = sA[tid] * a2;
            nb = fmaf(sA[tid], b2, sB[tid]);
        }
        __syncthreads();
        sA[tid] = na; sB[tid] = nb;
        __syncthreads();
    }

    // Carry entering this chunk from the right = value at element (tid+1)*CHUNK
    // = inclusive suffix B of thread tid+1 applied to initial carry 0.
    float carry = (tid + 1 < SCAN_THREADS) ? sB[tid + 1] : 0.0f;
    __syncthreads();   // before reusing sA/sB for reductions

    // Replay chunk with true carry, produce outputs + row moments.
    float sum = 0.0f, sq = 0.0f;
#pragma unroll
    for (int t = CHUNK - 1; t >= 0; t--) {
        carry = fmaf(a[t], carry, r[t]);
        r[t] = carry;            // reuse r[] as output buffer
        sum += carry;
        sq = fmaf(carry, carry, sq);
    }

    float4* o4 = reinterpret_cast<float4*>(out + row_off + base);
#pragma unroll
    for (int i = 0; i < CHUNK / 4; i++) {
        o4[i] = make_float4(r[i*4+0], r[i*4+1], r[i*4+2], r[i*4+3]);
    }

    // Block reduction of (sum, sq).
    sA[tid] = sum; sB[tid] = sq;
    __syncthreads();
#pragma unroll
    for (int s = SCAN_THREADS / 2; s > 0; s >>= 1) {
        if (tid < s) {
            sA[tid] += sA[tid + s];
            sB[tid] += sB[tid + s];
        }
        __syncthreads();
    }

    if (tid == 0) {
        float tsum = sA[0], tsq = sB[0];
        float mean = tsum / (float)T_LEN;
        float var  = (tsq - tsum * mean) / (float)(T_LEN - 1);   // ddof=1
        g_row_std[row] = sqrtf(fmaxf(var, 0.0f));
        atomicAdd(&g_sum, (double)tsum);
    }
}

// Normalize: (x - global_mean) / (row_std + eps). Operates on float4.
__global__ __launch_bounds__(256)
void norm_kernel(float* __restrict__ out)
{
    const float gmean = (float)(g_sum / ((double)B_ROWS * (double)T_LEN));
    const int n4 = B_ROWS * (T_LEN / 4);
    int i = blockIdx.x * blockDim.x + threadIdx.x;
    if (i >= n4) return;
    const int row = i >> 11;                   // / (T_LEN/4 = 2048)
    const float inv = 1.0f / (g_row_std[row] + EPS_N);
    float4 v = reinterpret_cast<float4*>(out)[i];
    v.x = (v.x - gmean) * inv;
    v.y = (v.y - gmean) * inv;
    v.z = (v.z - gmean) * inv;
    v.w = (v.w - gmean) * inv;
    reinterpret_cast<float4*>(out)[i] = v;
}

extern "C" void kernel_launch(void* const* d_in, const int* in_sizes, int n_in,
                              void* d_out, int out_size)
{
    const float* rewards = (const float*)d_in[0];
    const float* dones   = (const float*)d_in[1];
    float* out = (float*)d_out;

    init_kernel<<<1, 1>>>();
    scan_kernel<<<B_ROWS, SCAN_THREADS>>>(rewards, dones, out);
    const int n4 = B_ROWS * (T_LEN / 4);
    norm_kernel<<<(n4 + 255) / 256, 256>>>(out);
}

// round 2
// speedup vs baseline: 1.3145x; 1.3145x over previous
#include <cuda_runtime.h>
#include <math.h>

#define B_ROWS 4096
#define T_LEN  8192
#define SCAN_THREADS 512
#define NWARPS (SCAN_THREADS / 32)     // 16
#define CHUNK (T_LEN / SCAN_THREADS)   // 16
#define GAMMA 0.99f
#define EPS_N 1e-9f

// Scratch: per-row sum and 1/(std+eps), plus the global mean.
__device__ float g_row_sum[B_ROWS];
__device__ float g_row_inv[B_ROWS];
__device__ float g_mean_val;

// ───────────────────────── scan: one block per row ─────────────────────────
// x_t = r_t + a_t * x_{t+1},  a_t = GAMMA*(1-done_t).  Affine suffix scan.
__global__ __launch_bounds__(SCAN_THREADS, 2)
void scan_kernel(const float* __restrict__ rewards,
                 const float* __restrict__ dones,
                 float* __restrict__ out)
{
    const int row  = blockIdx.x;
    const int tid  = threadIdx.x;
    const int lane = tid & 31;
    const int wid  = tid >> 5;
    const size_t row_off = (size_t)row * T_LEN;
    const int base = tid * CHUNK;

    float r[CHUNK];
    float a[CHUNK];

    // Streaming (evict-first) vectorized loads: inputs are read exactly once.
    const float4* r4 = reinterpret_cast<const float4*>(rewards + row_off + base);
    const float4* d4 = reinterpret_cast<const float4*>(dones   + row_off + base);
#pragma unroll
    for (int i = 0; i < CHUNK / 4; i++) {
        float4 rv = __ldcs(r4 + i);
        float4 dv = __ldcs(d4 + i);
        r[i*4+0] = rv.x; r[i*4+1] = rv.y; r[i*4+2] = rv.z; r[i*4+3] = rv.w;
        a[i*4+0] = GAMMA * (1.0f - dv.x);
        a[i*4+1] = GAMMA * (1.0f - dv.y);
        a[i*4+2] = GAMMA * (1.0f - dv.z);
        a[i*4+3] = GAMMA * (1.0f - dv.w);
    }

    // Compose this thread's chunk into one affine map (A, B): x_left = B + A*x_right
    float A = 1.0f, Bc = 0.0f;
#pragma unroll
    for (int t = CHUNK - 1; t >= 0; t--) {
        Bc = fmaf(a[t], Bc, r[t]);
        A  = a[t] * A;
    }

    // ── warp-level inclusive SUFFIX scan via shuffles (5 steps, no barriers) ──
    // combine(self, next) : B = B_self + A_self*B_next ; A = A_self*A_next
#pragma unroll
    for (int d = 1; d < 32; d <<= 1) {
        float A2 = __shfl_down_sync(0xFFFFFFFFu, A, d);
        float B2 = __shfl_down_sync(0xFFFFFFFFu, Bc, d);
        if (lane + d < 32) {
            Bc = fmaf(A, B2, Bc);
            A  = A * A2;
        }
    }

    // Warp aggregates (lane 0's value) -> smem
    __shared__ float sWA[NWARPS];
    __shared__ float sWB[NWARPS];
    __shared__ float sCA[NWARPS];   // exclusive suffix carry per warp
    __shared__ float sCB[NWARPS];
    if (lane == 0) { sWA[wid] = A; sWB[wid] = Bc; }
    __syncthreads();

    // Warp 0 scans the 16 aggregates (inclusive suffix), writes EXCLUSIVE carries.
    if (wid == 0) {
        float wA = (lane < NWARPS) ? sWA[lane] : 1.0f;
        float wB = (lane < NWARPS) ? sWB[lane] : 0.0f;
#pragma unroll
        for (int d = 1; d < NWARPS; d <<= 1) {
            float A2 = __shfl_down_sync(0xFFFFFFFFu, wA, d);
            float B2 = __shfl_down_sync(0xFFFFFFFFu, wB, d);
            if (lane + d < NWARPS) {
                wB = fmaf(wA, B2, wB);
                wA = wA * A2;
            }
        }
        // exclusive carry for warp w = inclusive suffix of warp w+1 (identity for last warp)
        float eA = __shfl_down_sync(0xFFFFFFFFu, wA, 1);
        float eB = __shfl_down_sync(0xFFFFFFFFu, wB, 1);
        if (lane == NWARPS - 1) { eA = 1.0f; eB = 0.0f; }
        if (lane < NWARPS) { sCA[lane] = eA; sCB[lane] = eB; }
    }
    __syncthreads();

    // Total inclusive suffix for this thread = self ∘ warp_exclusive_carry
    float cA = sCA[wid], cB = sCB[wid];
    float totB = fmaf(A, cB, Bc);     // value of x at this thread's left edge (x_init=0)

    // Carry entering this thread's chunk = totB of thread tid+1.
    float carry = __shfl_down_sync(0xFFFFFFFFu, totB, 1);
    if (lane == 31) carry = cB;       // first thread of next warp == this warp's exclusive carry
    // (tid==511: cB==0 → carry 0, correct)

    // Replay chunk with true carry; produce outputs + row moments.
    float sum = 0.0f, sq = 0.0f;
#pragma unroll
    for (int t = CHUNK - 1; t >= 0; t--) {
        carry = fmaf(a[t], carry, r[t]);
        r[t] = carry;
        sum += carry;
        sq = fmaf(carry, carry, sq);
    }

    // Default stores: let the output allocate in L2 for the norm pass.
    float4* o4 = reinterpret_cast<float4*>(out + row_off + base);
#pragma unroll
    for (int i = 0; i < CHUNK / 4; i++)
        o4[i] = make_float4(r[i*4+0], r[i*4+1], r[i*4+2], r[i*4+3]);

    // Block reduction of (sum, sq): warp shuffles + one barrier.
#pragma unroll
    for (int d = 16; d > 0; d >>= 1) {
        sum += __shfl_down_sync(0xFFFFFFFFu, sum, d);
        sq  += __shfl_down_sync(0xFFFFFFFFu, sq,  d);
    }
    __shared__ float sS[NWARPS];
    __shared__ float sQ[NWARPS];
    if (lane == 0) { sS[wid] = sum; sQ[wid] = sq; }
    __syncthreads();
    if (wid == 0 && lane < NWARPS) {
        float ts = sS[lane], tq = sQ[lane];
#pragma unroll
        for (int d = NWARPS / 2; d > 0; d >>= 1) {
            ts += __shfl_down_sync(0xFFFFFFFFu, ts, d);
            tq += __shfl_down_sync(0xFFFFFFFFu, tq, d);
        }
        if (lane == 0) {
            float mean = ts / (float)T_LEN;
            float var  = (tq - ts * mean) / (float)(T_LEN - 1);   // ddof=1
            g_row_sum[row] = ts;
            g_row_inv[row] = 1.0f / (sqrtf(fmaxf(var, 0.0f)) + EPS_N);
        }
    }
}

// ─────────── tiny reduce: global mean from 4096 row sums (1 block) ───────────
__global__ __launch_bounds__(1024)
void reduce_kernel()
{
    const int tid = threadIdx.x;
    float s = 0.0f;
#pragma unroll
    for (int i = 0; i < B_ROWS / 1024; i++)
        s += g_row_sum[tid + i * 1024];
#pragma unroll
    for (int d = 16; d > 0; d >>= 1)
        s += __shfl_down_sync(0xFFFFFFFFu, s, d);
    __shared__ float sS[32];
    if ((tid & 31) == 0) sS[tid >> 5] = s;
    __syncthreads();
    if (tid < 32) {
        float t = sS[tid];
#pragma unroll
        for (int d = 16; d > 0; d >>= 1)
            t += __shfl_down_sync(0xFFFFFFFFu, t, d);
        if (tid == 0)
            g_mean_val = t / ((float)B_ROWS * (float)T_LEN);
    }
}

// ───────────── normalize: (x - gmean) * inv_row, float4, streaming out ─────────────
__global__ __launch_bounds__(512)
void norm_kernel(float* __restrict__ out)
{
    const float gmean = g_mean_val;
    const int n4 = B_ROWS * (T_LEN / 4);
    int i = blockIdx.x * blockDim.x + threadIdx.x;
    if (i >= n4) return;
    const int row = i >> 11;                 // / 2048
    const float inv = g_row_inv[row];
    const float neg = -gmean * inv;
    float4 v = reinterpret_cast<float4*>(out)[i];
    v.x = fmaf(v.x, inv, neg);
    v.y = fmaf(v.y, inv, neg);
    v.z = fmaf(v.z, inv, neg);
    v.w = fmaf(v.w, inv, neg);
    __stcs(reinterpret_cast<float4*>(out) + i, v);
}

extern "C" void kernel_launch(void* const* d_in, const int* in_sizes, int n_in,
                              void* d_out, int out_size)
{
    const float* rewards = (const float*)d_in[0];
    const float* dones   = (const float*)d_in[1];
    float* out = (float*)d_out;

    scan_kernel<<<B_ROWS, SCAN_THREADS>>>(rewards, dones, out);
    reduce_kernel<<<1, 1024>>>();
    const int n4 = B_ROWS * (T_LEN / 4);
    norm_kernel<<<n4 / 512, 512>>>(out);
}

// round 3
// speedup vs baseline: 1.3462x; 1.0241x over previous
#include <cuda_runtime.h>
#include <math.h>

#define B_ROWS 4096
#define T_LEN  8192
#define SCAN_THREADS 512
#define NWARPS (SCAN_THREADS / 32)     // 16
#define CHUNK (T_LEN / SCAN_THREADS)   // 16
#define GAMMA 0.99f
#define GAMMA16 0.8514577710948755f    // 0.99^16
#define EPS_N 1e-9f

// Scratch: per-row sum and 1/(std+eps), global mean, completion ticket.
__device__ float    g_row_sum[B_ROWS];
__device__ float    g_row_inv[B_ROWS];
__device__ float    g_mean_val;
__device__ unsigned g_count;           // zero-init; atomicInc wraps -> self-reset per launch

// ───────────────────────── scan: one block per row ─────────────────────────
// x_t = r_t + a_t * x_{t+1},  a_t = GAMMA*(1-done_t),  done in {0,1} exactly.
__global__ __launch_bounds__(SCAN_THREADS, 3)
void scan_kernel(const float* __restrict__ rewards,
                 const float* __restrict__ dones,
                 float* __restrict__ out)
{
    const int row  = blockIdx.x;
    const int tid  = threadIdx.x;
    const int lane = tid & 31;
    const int wid  = tid >> 5;
    const size_t row_off = (size_t)row * T_LEN;
    const int base = tid * CHUNK;

    float r[CHUNK];
    unsigned mask = 0;                 // bit t set -> done_t == 1 -> a_t == 0

    const float4* r4 = reinterpret_cast<const float4*>(rewards + row_off + base);
    const float4* d4 = reinterpret_cast<const float4*>(dones   + row_off + base);
#pragma unroll
    for (int i = 0; i < CHUNK / 4; i++) {
        float4 rv = __ldcs(r4 + i);
        float4 dv = __ldcs(d4 + i);
        r[i*4+0] = rv.x; r[i*4+1] = rv.y; r[i*4+2] = rv.z; r[i*4+3] = rv.w;
        mask |= (dv.x != 0.0f ? 1u : 0u) << (i*4+0);
        mask |= (dv.y != 0.0f ? 1u : 0u) << (i*4+1);
        mask |= (dv.z != 0.0f ? 1u : 0u) << (i*4+2);
        mask |= (dv.w != 0.0f ? 1u : 0u) << (i*4+3);
    }

    // Compose chunk into affine map (A, B): x_left = B + A * x_right.
    // A = gamma^16 if no done in chunk else 0 (any a_t == 0 kills the product).
    float A  = (mask == 0u) ? GAMMA16 : 0.0f;
    float Bc = 0.0f;
#pragma unroll
    for (int t = CHUNK - 1; t >= 0; t--) {
        float f = fmaf(GAMMA, Bc, r[t]);
        Bc = (mask & (1u << t)) ? r[t] : f;   // a_t==0 -> carry reset
    }

    // Warp-level inclusive SUFFIX scan via shuffles.
#pragma unroll
    for (int d = 1; d < 32; d <<= 1) {
        float A2 = __shfl_down_sync(0xFFFFFFFFu, A, d);
        float B2 = __shfl_down_sync(0xFFFFFFFFu, Bc, d);
        if (lane + d < 32) {
            Bc = fmaf(A, B2, Bc);
            A  = A * A2;
        }
    }

    __shared__ float sWA[NWARPS];
    __shared__ float sWB[NWARPS];
    __shared__ float sCB[NWARPS];      // exclusive suffix carry (B only needed)
    if (lane == 0) { sWA[wid] = A; sWB[wid] = Bc; }
    __syncthreads();

    if (wid == 0) {
        float wA = (lane < NWARPS) ? sWA[lane] : 1.0f;
        float wB = (lane < NWARPS) ? sWB[lane] : 0.0f;
#pragma unroll
        for (int d = 1; d < NWARPS; d <<= 1) {
            float A2 = __shfl_down_sync(0xFFFFFFFFu, wA, d);
            float B2 = __shfl_down_sync(0xFFFFFFFFu, wB, d);
            if (lane + d < NWARPS) {
                wB = fmaf(wA, B2, wB);
                wA = wA * A2;
            }
        }
        float eB = __shfl_down_sync(0xFFFFFFFFu, wB, 1);
        if (lane == NWARPS - 1) eB = 0.0f;
        if (lane < NWARPS) sCB[lane] = eB;
    }
    __syncthreads();

    float cB   = sCB[wid];
    float totB = fmaf(A, cB, Bc);          // value at this thread's left edge
    float carry = __shfl_down_sync(0xFFFFFFFFu, totB, 1);
    if (lane == 31) carry = cB;            // tid==511 -> cB==0, correct

    // Replay chunk with true carry; values + row moments.
    float sum = 0.0f, sq = 0.0f;
#pragma unroll
    for (int t = CHUNK - 1; t >= 0; t--) {
        float f = fmaf(GAMMA, carry, r[t]);
        carry = (mask & (1u << t)) ? r[t] : f;
        r[t] = carry;
        sum += carry;
        sq = fmaf(carry, carry, sq);
    }

    float4* o4 = reinterpret_cast<float4*>(out + row_off + base);
#pragma unroll
    for (int i = 0; i < CHUNK / 4; i++)
        o4[i] = make_float4(r[i*4+0], r[i*4+1], r[i*4+2], r[i*4+3]);

    // Block reduction of (sum, sq).
#pragma unroll
    for (int d = 16; d > 0; d >>= 1) {
        sum += __shfl_down_sync(0xFFFFFFFFu, sum, d);
        sq  += __shfl_down_sync(0xFFFFFFFFu, sq,  d);
    }
    __shared__ float sS[NWARPS];
    __shared__ float sQ[NWARPS];
    if (lane == 0) { sS[wid] = sum; sQ[wid] = sq; }
    __syncthreads();
    if (tid < 32) {
        float ts = (lane < NWARPS) ? sS[lane] : 0.0f;
        float tq = (lane < NWARPS) ? sQ[lane] : 0.0f;
#pragma unroll
        for (int d = NWARPS / 2; d > 0; d >>= 1) {
            ts += __shfl_down_sync(0xFFFFFFFFu, ts, d);
            tq += __shfl_down_sync(0xFFFFFFFFu, tq, d);
        }
        if (lane == 0) {
            float mean = ts / (float)T_LEN;
            float var  = (tq - ts * mean) / (float)(T_LEN - 1);   // ddof=1
            g_row_sum[row] = ts;
            g_row_inv[row] = 1.0f / (sqrtf(fmaxf(var, 0.0f)) + EPS_N);
        }
    }

    // ── last block to finish reduces the 4096 row sums to the global mean ──
    __shared__ unsigned s_last;
    if (tid == 0) {
        __threadfence();
        unsigned prev = atomicInc(&g_count, B_ROWS - 1);   // wraps to 0: self-reset
        s_last = (prev == B_ROWS - 1) ? 1u : 0u;
    }
    __syncthreads();
    if (s_last) {
        float s = 0.0f;
#pragma unroll
        for (int i = 0; i < B_ROWS / SCAN_THREADS; i++)
            s += __ldcg(&g_row_sum[tid + i * SCAN_THREADS]);
#pragma unroll
        for (int d = 16; d > 0; d >>= 1)
            s += __shfl_down_sync(0xFFFFFFFFu, s, d);
        if (lane == 0) sS[wid] = s;
        __syncthreads();
        if (tid < 32) {
            float t = (lane < NWARPS) ? sS[lane] : 0.0f;
#pragma unroll
            for (int d = 16; d > 0; d >>= 1)
                t += __shfl_down_sync(0xFFFFFFFFu, t, d);
            if (tid == 0)
                g_mean_val = t / ((float)B_ROWS * (float)T_LEN);
        }
    }
}

// ───────────── normalize: (x - gmean) * inv_row, float4, streaming out ─────────────
__global__ __launch_bounds__(512)
void norm_kernel(float* __restrict__ out)
{
    const float gmean = g_mean_val;
    const int n4 = B_ROWS * (T_LEN / 4);
    int i = blockIdx.x * blockDim.x + threadIdx.x;
    if (i >= n4) return;
    const int row = i >> 11;                 // / 2048
    const float inv = g_row_inv[row];
    const float neg = -gmean * inv;
    float4 v = reinterpret_cast<float4*>(out)[i];
    v.x = fmaf(v.x, inv, neg);
    v.y = fmaf(v.y, inv, neg);
    v.z = fmaf(v.z, inv, neg);
    v.w = fmaf(v.w, inv, neg);
    __stcs(reinterpret_cast<float4*>(out) + i, v);
}

extern "C" void kernel_launch(void* const* d_in, const int* in_sizes, int n_in,
                              void* d_out, int out_size)
{
    const float* rewards = (const float*)d_in[0];
    const float* dones   = (const float*)d_in[1];
    float* out = (float*)d_out;

    scan_kernel<<<B_ROWS, SCAN_THREADS>>>(rewards, dones, out);
    const int n4 = B_ROWS * (T_LEN / 4);
    norm_kernel<<<n4 / 512, 512>>>(out);
}

// round 4
// speedup vs baseline: 1.4881x; 1.1054x over previous
#include <cuda_runtime.h>
#include <cuda_fp16.h>
#include <math.h>

#define B_ROWS 4096
#define T_LEN  8192
#define SCAN_THREADS 512
#define NWARPS (SCAN_THREADS / 32)     // 16
#define CHUNK (T_LEN / SCAN_THREADS)   // 16
#define GAMMA 0.99f
#define GAMMA16 0.8514577710948755f    // 0.99^16
#define EPS_N 1e-9f

// Scratch (device globals; no allocations allowed).
__device__ float    g_row_sum[B_ROWS];
__device__ float    g_row_inv[B_ROWS];
__device__ float    g_mean_val;
__device__ unsigned g_count;           // zero-init; atomicInc wraps -> self-reset per launch
// fp16 staging for unnormalized returns: 64 MB, fits in L2 (126 MB).
__device__ __align__(16) __half g_ret_h[(size_t)B_ROWS * T_LEN];

// ───────────────────────── scan: one block per row ─────────────────────────
// x_t = r_t + a_t * x_{t+1},  a_t = GAMMA*(1-done_t),  done in {0,1} exactly.
__global__ __launch_bounds__(SCAN_THREADS, 3)
void scan_kernel(const float* __restrict__ rewards,
                 const float* __restrict__ dones)
{
    const int row  = blockIdx.x;
    const int tid  = threadIdx.x;
    const int lane = tid & 31;
    const int wid  = tid >> 5;
    const size_t row_off = (size_t)row * T_LEN;
    const int base = tid * CHUNK;

    float r[CHUNK];
    unsigned mask = 0;                 // bit t set -> done_t == 1 -> a_t == 0

    const float4* r4 = reinterpret_cast<const float4*>(rewards + row_off + base);
    const float4* d4 = reinterpret_cast<const float4*>(dones   + row_off + base);
#pragma unroll
    for (int i = 0; i < CHUNK / 4; i++) {
        float4 rv = __ldcs(r4 + i);
        float4 dv = __ldcs(d4 + i);
        r[i*4+0] = rv.x; r[i*4+1] = rv.y; r[i*4+2] = rv.z; r[i*4+3] = rv.w;
        mask |= (dv.x != 0.0f ? 1u : 0u) << (i*4+0);
        mask |= (dv.y != 0.0f ? 1u : 0u) << (i*4+1);
        mask |= (dv.z != 0.0f ? 1u : 0u) << (i*4+2);
        mask |= (dv.w != 0.0f ? 1u : 0u) << (i*4+3);
    }

    // Compose chunk into affine map (A, B): x_left = B + A * x_right.
    float A  = (mask == 0u) ? GAMMA16 : 0.0f;
    float Bc = 0.0f;
#pragma unroll
    for (int t = CHUNK - 1; t >= 0; t--) {
        float f = fmaf(GAMMA, Bc, r[t]);
        Bc = (mask & (1u << t)) ? r[t] : f;
    }

    // Warp-level inclusive SUFFIX scan via shuffles.
#pragma unroll
    for (int d = 1; d < 32; d <<= 1) {
        float A2 = __shfl_down_sync(0xFFFFFFFFu, A, d);
        float B2 = __shfl_down_sync(0xFFFFFFFFu, Bc, d);
        if (lane + d < 32) {
            Bc = fmaf(A, B2, Bc);
            A  = A * A2;
        }
    }

    __shared__ float sWA[NWARPS];
    __shared__ float sWB[NWARPS];
    __shared__ float sCB[NWARPS];
    if (lane == 0) { sWA[wid] = A; sWB[wid] = Bc; }
    __syncthreads();

    if (wid == 0) {
        float wA = (lane < NWARPS) ? sWA[lane] : 1.0f;
        float wB = (lane < NWARPS) ? sWB[lane] : 0.0f;
#pragma unroll
        for (int d = 1; d < NWARPS; d <<= 1) {
            float A2 = __shfl_down_sync(0xFFFFFFFFu, wA, d);
            float B2 = __shfl_down_sync(0xFFFFFFFFu, wB, d);
            if (lane + d < NWARPS) {
                wB = fmaf(wA, B2, wB);
                wA = wA * A2;
            }
        }
        float eB = __shfl_down_sync(0xFFFFFFFFu, wB, 1);
        if (lane == NWARPS - 1) eB = 0.0f;
        if (lane < NWARPS) sCB[lane] = eB;
    }
    __syncthreads();

    float cB   = sCB[wid];
    float totB = fmaf(A, cB, Bc);
    float carry = __shfl_down_sync(0xFFFFFFFFu, totB, 1);
    if (lane == 31) carry = cB;        // tid==511 -> cB==0, correct

    // Replay chunk with true carry; values + row moments (f32 precision).
    float sum = 0.0f, sq = 0.0f;
#pragma unroll
    for (int t = CHUNK - 1; t >= 0; t--) {
        float f = fmaf(GAMMA, carry, r[t]);
        carry = (mask & (1u << t)) ? r[t] : f;
        r[t] = carry;
        sum += carry;
        sq = fmaf(carry, carry, sq);
    }

    // fp16 staging store (default policy -> allocate in L2; consumed by norm).
    __half2 h[CHUNK / 2];
#pragma unroll
    for (int i = 0; i < CHUNK / 2; i++)
        h[i] = __floats2half2_rn(r[2*i], r[2*i+1]);
    uint4* dst = reinterpret_cast<uint4*>(g_ret_h + row_off + base);
    const uint4* src = reinterpret_cast<const uint4*>(h);
    dst[0] = src[0];
    dst[1] = src[1];

    // Block reduction of (sum, sq).
#pragma unroll
    for (int d = 16; d > 0; d >>= 1) {
        sum += __shfl_down_sync(0xFFFFFFFFu, sum, d);
        sq  += __shfl_down_sync(0xFFFFFFFFu, sq,  d);
    }
    __shared__ float sS[NWARPS];
    __shared__ float sQ[NWARPS];
    if (lane == 0) { sS[wid] = sum; sQ[wid] = sq; }
    __syncthreads();
    if (tid < 32) {
        float ts = (lane < NWARPS) ? sS[lane] : 0.0f;
        float tq = (lane < NWARPS) ? sQ[lane] : 0.0f;
#pragma unroll
        for (int d = NWARPS / 2; d > 0; d >>= 1) {
            ts += __shfl_down_sync(0xFFFFFFFFu, ts, d);
            tq += __shfl_down_sync(0xFFFFFFFFu, tq, d);
        }
        if (lane == 0) {
            float mean = ts / (float)T_LEN;
            float var  = (tq - ts * mean) / (float)(T_LEN - 1);   // ddof=1
            g_row_sum[row] = ts;
            g_row_inv[row] = 1.0f / (sqrtf(fmaxf(var, 0.0f)) + EPS_N);
        }
    }

    // Last block to finish reduces the 4096 row sums -> global mean.
    __shared__ unsigned s_last;
    if (tid == 0) {
        __threadfence();
        unsigned prev = atomicInc(&g_count, B_ROWS - 1);
        s_last = (prev == B_ROWS - 1) ? 1u : 0u;
    }
    __syncthreads();
    if (s_last) {
        float s = 0.0f;
#pragma unroll
        for (int i = 0; i < B_ROWS / SCAN_THREADS; i++)
            s += __ldcg(&g_row_sum[tid + i * SCAN_THREADS]);
#pragma unroll
        for (int d = 16; d > 0; d >>= 1)
            s += __shfl_down_sync(0xFFFFFFFFu, s, d);
        if (lane == 0) sS[wid] = s;
        __syncthreads();
        if (tid < 32) {
            float t = (lane < NWARPS) ? sS[lane] : 0.0f;
#pragma unroll
            for (int d = 16; d > 0; d >>= 1)
                t += __shfl_down_sync(0xFFFFFFFFu, t, d);
            if (tid == 0)
                g_mean_val = t / ((float)B_ROWS * (float)T_LEN);
        }
    }
}

// ── normalize: read fp16 staging (L2-resident), write f32 out (streaming) ──
// Each thread handles 16 contiguous elements: 2 independent uint4 loads (MLP=2).
#define NORM_ELEMS 16
__global__ __launch_bounds__(512)
void norm_kernel(float* __restrict__ out)
{
    const float gmean = g_mean_val;
    const int i = blockIdx.x * blockDim.x + threadIdx.x;
    const size_t base = (size_t)i * NORM_ELEMS;
    const int row = (int)(base >> 13);           // / T_LEN
    const float inv = g_row_inv[row];
    const float neg = -gmean * inv;

    const uint4* src = reinterpret_cast<const uint4*>(g_ret_h + base);
    uint4 u0 = src[0];
    uint4 u1 = src[1];

    const __half2* h0 = reinterpret_cast<const __half2*>(&u0);
    const __half2* h1 = reinterpret_cast<const __half2*>(&u1);

    float4* o4 = reinterpret_cast<float4*>(out + base);
    float4 v;
#pragma unroll
    for (int j = 0; j < 2; j++) {
        float2 a = __half22float2(h0[2*j+0]);
        float2 b = __half22float2(h0[2*j+1]);
        v.x = fmaf(a.x, inv, neg); v.y = fmaf(a.y, inv, neg);
        v.z = fmaf(b.x, inv, neg); v.w = fmaf(b.y, inv, neg);
        __stcs(o4 + j, v);
    }
#pragma unroll
    for (int j = 0; j < 2; j++) {
        float2 a = __half22float2(h1[2*j+0]);
        float2 b = __half22float2(h1[2*j+1]);
        v.x = fmaf(a.x, inv, neg); v.y = fmaf(a.y, inv, neg);
        v.z = fmaf(b.x, inv, neg); v.w = fmaf(b.y, inv, neg);
        __stcs(o4 + 2 + j, v);
    }
}

extern "C" void kernel_launch(void* const* d_in, const int* in_sizes, int n_in,
                              void* d_out, int out_size)
{
    const float* rewards = (const float*)d_in[0];
    const float* dones   = (const float*)d_in[1];
    float* out = (float*)d_out;

    scan_kernel<<<B_ROWS, SCAN_THREADS>>>(rewards, dones);
    const int nthreads = B_ROWS * (T_LEN / NORM_ELEMS);   // 2M
    norm_kernel<<<nthreads / 512, 512>>>(out);
}